// round 8
// baseline (speedup 1.0000x reference)
#include <cuda_runtime.h>
#include <math.h>

#define LDIM     1024
#define NROWS    32768      // B*D = 64*512
#define NBLK_DOT 4096       // NROWS / 8 rows-per-block
#define NBLK_EPI 128        // 128 * 256 = NROWS
#define NBLK_TOT (NBLK_DOT + NBLK_EPI)

// Scratch (allocation-free per harness rules)
__device__ float    g_att[NROWS];
__device__ float2   g_partial[NBLK_DOT];
__device__ unsigned g_done = 0;   // monotonic: +NBLK_DOT per replay
__device__ unsigned g_gen  = 0;   // monotonic: +NBLK_EPI per replay

__global__ void __launch_bounds__(256)
fused_kernel(const float4* __restrict__ x,
             const float*  __restrict__ fc_w,
             const float*  __restrict__ fc_b,
             const float*  __restrict__ bn_gamma,
             const float*  __restrict__ bn_beta,
             const float*  __restrict__ conv_w,
             const float*  __restrict__ conv_b,
             float* __restrict__ out, int out_size) {
    const int t    = threadIdx.x;
    const int warp = t >> 5;
    const int lane = t & 31;
    const int bid  = blockIdx.x;

    if (bid < NBLK_DOT) {
        // ================= DOT BLOCK: 8 rows, one warp per row =============
        __shared__ float sw[LDIM];
        __shared__ float s_att[8];

        // w[l] = sqrt(2/L)*(fc_w0/sqrt2 + sum_{k=1..4} fc_wk*cos(k*ph)),
        // Chebyshev recurrence: one cosf per element.
        {
            const float sqrt2L = sqrtf(2.0f / (float)LDIM);
            const float pi = 3.14159265358979323846f;
            float w0 = fc_w[0] * 0.70710678118654752f;
            float w1 = fc_w[1], w2 = fc_w[2], w3 = fc_w[3], w4 = fc_w[4];
#pragma unroll
            for (int j = 0; j < 4; j++) {
                int l = t + j * 256;
                float ph = pi * ((float)l + 0.5f) / (float)LDIM;
                float c1 = cosf(ph);
                float c2 = 2.0f * c1 * c1 - 1.0f;
                float c3 = 2.0f * c1 * c2 - c1;
                float c4 = 2.0f * c1 * c3 - c2;
                sw[l] = sqrt2L * (w0 + w1 * c1 + w2 * c2 + w3 * c3 + w4 * c4);
            }
        }
        __syncthreads();

        int row = bid * 8 + warp;
        const float4* xr = x + (size_t)row * (LDIM / 4);
        const float4* wr = (const float4*)sw;

        float acc = 0.0f;
#pragma unroll
        for (int j = 0; j < 8; j++) {
            int idx = j * 32 + lane;
            float4 v = __ldcs(xr + idx);
            float4 w = wr[idx];
            acc += v.x * w.x + v.y * w.y + v.z * w.z + v.w * w.w;
        }
#pragma unroll
        for (int off = 16; off; off >>= 1)
            acc += __shfl_xor_sync(0xffffffffu, acc, off);

        float att = acc + fc_b[0];
        if (lane == 0) {
            g_att[row] = att;
            s_att[warp] = att;
        }
        __syncthreads();

        if (t == 0) {
            float s = 0.0f, q = 0.0f;
#pragma unroll
            for (int i = 0; i < 8; i++) {
                float v = s_att[i];
                s += v;
                q += v * v;
            }
            g_partial[bid] = make_float2(s, q);
            __threadfence();                    // partial visible before arrive
            atomicAdd(&g_done, 1u);
        }
    } else {
        // ================= EPILOGUE BLOCK: wait, stats, 256 rows ============
        __shared__ float s_ws[8], s_wq[8];
        __shared__ float s_mi[2];

        if (t == 0) {
            // derive this replay's completion target (monotonic, reset-free)
            unsigned old = atomicAdd(&g_gen, 1u);
            unsigned gen = old / NBLK_EPI;
            unsigned target = (gen + 1u) * NBLK_DOT;
            unsigned c;
            for (;;) {
                asm volatile("ld.acquire.gpu.u32 %0, [%1];" : "=r"(c) : "l"(&g_done));
                if (c >= target) break;
                __nanosleep(128);               // gentle backoff while dot runs
            }
        }
        __syncthreads();

        // Redundant stats reduction: 256 threads x 16 partials, fixed order.
        float s = 0.0f, q = 0.0f;
#pragma unroll
        for (int j = 0; j < NBLK_DOT / 256; j++) {
            float2 p = __ldcg(&g_partial[t + j * 256]);
            s += p.x;
            q += p.y;
        }
#pragma unroll
        for (int off = 16; off; off >>= 1) {
            s += __shfl_xor_sync(0xffffffffu, s, off);
            q += __shfl_xor_sync(0xffffffffu, q, off);
        }
        if (lane == 0) { s_ws[warp] = s; s_wq[warp] = q; }
        __syncthreads();
        if (warp == 0 && lane < 8) {
            float ss = s_ws[lane], qq = s_wq[lane];
#pragma unroll
            for (int off = 4; off; off >>= 1) {
                ss += __shfl_xor_sync(0xffu, ss, off);
                qq += __shfl_xor_sync(0xffu, qq, off);
            }
            if (lane == 0) {
                float mean = ss / (float)NROWS;
                float var  = qq / (float)NROWS - mean * mean;
                s_mi[0] = mean;
                s_mi[1] = rsqrtf(var + 1e-5f);
            }
        }
        __syncthreads();

        int i = (bid - NBLK_DOT) * 256 + t;     // 128*256 == NROWS
        float a = (__ldcg(&g_att[i]) - s_mi[0]) * s_mi[1] * bn_gamma[0] + bn_beta[0];
        a = 0.5f * a * (1.0f + erff(a * 0.70710678118654752f));
        float z = a * conv_w[0] + conv_b[0];
        float g = 1.0f / (1.0f + expf(-z));
        out[i] = g;
        if (out_size >= 2 * NROWS) out[i + NROWS] = g;
    }
}

// ---------------------------------------------------------------------------
// Inputs (metadata order): x[64,512,1024] f32, fc_w[5], fc_b[1],
//                          bn_gamma[1], bn_beta[1], conv_w[1], conv_b[1]
// Output: (att1, att2) each [B, D, 1] -> 2*32768 f32
// ---------------------------------------------------------------------------
extern "C" void kernel_launch(void* const* d_in, const int* in_sizes, int n_in,
                              void* d_out, int out_size) {
    const float4* x        = (const float4*)d_in[0];
    const float*  fc_w     = (const float*)d_in[1];
    const float*  fc_b     = (const float*)d_in[2];
    const float*  bn_gamma = (const float*)d_in[3];
    const float*  bn_beta  = (const float*)d_in[4];
    const float*  conv_w   = (const float*)d_in[5];
    const float*  conv_b   = (const float*)d_in[6];
    float* out = (float*)d_out;

    fused_kernel<<<NBLK_TOT, 256>>>(x, fc_w, fc_b, bn_gamma, bn_beta,
                                    conv_w, conv_b, out, out_size);
}